// round 12
// baseline (speedup 1.0000x reference)
#include <cuda_runtime.h>

// Stacked LSTM: B=64, T=512, D=256, H=512, 3 layers. fp32.
// Persistent kernel, 128 blocks x 1024 threads.
// x-projections precomputed / pipelined as "filler":
//   P0: xw0[bc][t][b][16] = x @ W0 (block-private, barrier-free)
//   rec layer l (K=512, h only): per step a 64x32x512 GEMM:
//     cols 0-15  = h_t @ U_l      (critical: gates -> h_{t+1})
//     cols 16-31 = h_t @ W_{l+1}  (filler: next layer's xw, index t-1)
//   layer 2: 16-way k-split, 16 cols (rec only).
// Weights resident in smem. h panel double-buffered 128-k chunks.
// Split-phase two-level grid barrier; xw tile prefetched before wait.
// (R11 fix: zred row strides must be EVEN for float2 stores: 34 / 18.)

#define Bsz 64
#define Tsz 512
#define Dsz 256
#define Hsz 512
#define Gsz 2048
#define NBLK 128
#define NTHR 1024

typedef unsigned long long u64;

// smem floats: w_s [512][32] 16384 | a_s [2][64][132] 16896 | zred 18432 | bias 16
#define SM_WS 0
#define SM_AS 16384
#define SM_ZR (16384 + 16896)
#define SM_BIAS (16384 + 16896 + 18432)
#define SMEM_FLOATS (SM_BIAS + 16)
#define SMEM_BYTES (SMEM_FLOATS * 4)
#define ASTRIDE 132
#define ABUF (64 * ASTRIDE)

__device__ float g_xwA[(size_t)NBLK * Tsz * Bsz * 16];   // 256 MB
__device__ float g_xwB[(size_t)NBLK * Tsz * Bsz * 16];   // 256 MB
__device__ float g_hbuf[2][Bsz * Hsz];
__device__ unsigned g_cnt[8];
__device__ unsigned g_root = 0;
__device__ unsigned g_gen = 0;

__device__ __forceinline__ void bar_arrive(unsigned* s_my, int grp) {
    __syncthreads();
    if (threadIdx.x == 0) {
        unsigned my;
        asm volatile("ld.relaxed.gpu.u32 %0, [%1];" : "=r"(my) : "l"(&g_gen));
        *s_my = my;
        __threadfence();
        unsigned old = atomicAdd(&g_cnt[grp], 1u);
        if (old == 15u) {
            unsigned rold = atomicAdd(&g_root, 1u);
            if (rold == 7u) {
                #pragma unroll
                for (int i = 0; i < 8; i++) g_cnt[i] = 0;
                g_root = 0;
                __threadfence();
                asm volatile("st.release.gpu.u32 [%0], %1;" :: "l"(&g_gen), "r"(my + 1u));
            }
        }
    }
}
__device__ __forceinline__ void bar_wait(unsigned* s_my) {
    if (threadIdx.x == 0) {
        unsigned my = *s_my, g;
        do {
            asm volatile("ld.acquire.gpu.u32 %0, [%1];" : "=r"(g) : "l"(&g_gen));
        } while (g == my);
    }
    __syncthreads();
}

__device__ __forceinline__ float fsig(float x) {
    return __fdividef(1.0f, 1.0f + __expf(-x));
}
__device__ __forceinline__ float ftanh(float x) {
    float e = __expf(2.0f * x);
    return 1.0f - __fdividef(2.0f, e + 1.0f);
}
__device__ __forceinline__ void fma2(u64& d, u64 a, u64 b) {
    asm("fma.rn.f32x2 %0, %1, %2, %0;" : "+l"(d) : "l"(a), "l"(b));
}
__device__ __forceinline__ u64 rep2(float x) {
    u64 r;
    asm("mov.b64 %0, {%1, %1};" : "=l"(r) : "f"(x));
    return r;
}

extern "C" __global__ void __launch_bounds__(NTHR, 1)
lstm_kernel(const float* __restrict__ x0,
            const float* __restrict__ W0, const float* __restrict__ U0, const float* __restrict__ b0,
            const float* __restrict__ W1, const float* __restrict__ U1, const float* __restrict__ b1,
            const float* __restrict__ W2, const float* __restrict__ U2, const float* __restrict__ b2,
            float* __restrict__ out)
{
    extern __shared__ float smem[];
    float* w_s    = smem + SM_WS;    // [k][32]
    float* a_s    = smem + SM_AS;    // [2][64][ASTRIDE]
    float* zred   = smem + SM_ZR;    // FIL: [8][64][34] / 16-way: [16][64][18]
    float* bias_s = smem + SM_BIAS;
    __shared__ unsigned s_my;

    const int tid  = threadIdx.x;
    const int bc   = blockIdx.x;
    const int grp  = bc >> 4;
    const int j0   = bc * 4;
    const int wid  = tid >> 5;
    const int lane = tid & 31;
    const int kg   = wid >> 2;               // 0..7
    const int rq   = wid & 3;                // 0..3
    const int rp   = lane >> 2;              // 0..7
    const int cq   = lane & 3;               // 0..3
    const int kg2  = kg * 2 + (cq >> 1);     // 0..15 (16-way variant)
    const int rowA = rq * 16 + rp;           // rows rowA, rowA+8
    const int srow = tid >> 5;               // staging row 0..31 (+32)
    const int sk4  = (tid & 31) * 4;         // staging k offset 0..124
    const int gb   = (tid & 255) >> 2;       // gather batch
    const int gj   = tid & 3;                // gather unit
    const int xb   = tid >> 2;               // P0/tail xw-gather batch (tid<256)
    const int xcp  = tid & 3;                // xw-gather col group

    // ---------------- staging / compute building blocks ----------------
    float4 st[2];
    #define LDG_H(CI)                                                             \
        do { const float* s_ = hsrc + (CI) * 128 + sk4;                           \
             st[0] = *(const float4*)(s_ + srow * Hsz);                           \
             st[1] = *(const float4*)(s_ + (srow + 32) * Hsz); } while (0)
    #define LDG_X0(TT, CI)                                                        \
        do { const float* s_ = x0 + (CI) * 128 + sk4;                             \
             st[0] = *(const float4*)(s_ + ((size_t)srow * Tsz + (TT)) * Dsz);    \
             st[1] = *(const float4*)(s_ + ((size_t)(srow + 32) * Tsz + (TT)) * Dsz); } while (0)
    #define STS_A(BUF)                                                            \
        do { float* d_ = a_s + (BUF) * ABUF + srow * ASTRIDE + sk4;               \
             *(float4*)d_ = st[0];                                                \
             *(float4*)(d_ + 32 * ASTRIDE) = st[1]; } while (0)

    // 8-way ksplit, 32 cols (rec 0-15 + filler 16-31)
    #define COMPUTE_FIL(BUF, CI)                                                  \
        do {                                                                      \
            const float* ab_ = a_s + (BUF) * ABUF + rowA * ASTRIDE + kg * 16;     \
            const float* wb_ = w_s + ((CI) * 128 + kg * 16) * 32 + cq * 8;        \
            _Pragma("unroll")                                                     \
            for (int kq = 0; kq < 4; kq++) {                                      \
                float4 a0 = *(const float4*)(ab_ + kq * 4);                       \
                float4 a1 = *(const float4*)(ab_ + 8 * ASTRIDE + kq * 4);         \
                _Pragma("unroll")                                                 \
                for (int j = 0; j < 4; j++) {                                     \
                    const float* wr_ = wb_ + (kq * 4 + j) * 32;                   \
                    ulonglong2 wlo = *(const ulonglong2*)wr_;                     \
                    ulonglong2 whi = *(const ulonglong2*)(wr_ + 4);               \
                    u64 ar0 = rep2(((const float*)&a0)[j]);                       \
                    u64 ar1 = rep2(((const float*)&a1)[j]);                       \
                    fma2(acc[0][0], ar0, wlo.x); fma2(acc[0][1], ar0, wlo.y);     \
                    fma2(acc[0][2], ar0, whi.x); fma2(acc[0][3], ar0, whi.y);     \
                    fma2(acc[1][0], ar1, wlo.x); fma2(acc[1][1], ar1, wlo.y);     \
                    fma2(acc[1][2], ar1, whi.x); fma2(acc[1][3], ar1, whi.y);     \
                }                                                                 \
            }                                                                     \
        } while (0)

    // 16-way ksplit, 16 cols starting at w column WBASE
    #define COMPUTE_16(BUF, CI, WBASE)                                            \
        do {                                                                      \
            const float* ab_ = a_s + (BUF) * ABUF + rowA * ASTRIDE + kg2 * 8;     \
            const float* wb_ = w_s + ((CI) * 128 + kg2 * 8) * 32 + (WBASE) + (cq & 1) * 8; \
            _Pragma("unroll")                                                     \
            for (int kq = 0; kq < 2; kq++) {                                      \
                float4 a0 = *(const float4*)(ab_ + kq * 4);                       \
                float4 a1 = *(const float4*)(ab_ + 8 * ASTRIDE + kq * 4);         \
                _Pragma("unroll")                                                 \
                for (int j = 0; j < 4; j++) {                                     \
                    const float* wr_ = wb_ + (kq * 4 + j) * 32;                   \
                    ulonglong2 wlo = *(const ulonglong2*)wr_;                     \
                    ulonglong2 whi = *(const ulonglong2*)(wr_ + 4);               \
                    u64 ar0 = rep2(((const float*)&a0)[j]);                       \
                    u64 ar1 = rep2(((const float*)&a1)[j]);                       \
                    fma2(acc[0][0], ar0, wlo.x); fma2(acc[0][1], ar0, wlo.y);     \
                    fma2(acc[0][2], ar0, whi.x); fma2(acc[0][3], ar0, whi.y);     \
                    fma2(acc[1][0], ar1, wlo.x); fma2(acc[1][1], ar1, wlo.y);     \
                    fma2(acc[1][2], ar1, whi.x); fma2(acc[1][3], ar1, whi.y);     \
                }                                                                 \
            }                                                                     \
        } while (0)

    // even strides: FIL group 64*34=2176, 16-way group 64*18=1152
    #define ZRED_FIL()                                                            \
        do { _Pragma("unroll")                                                    \
             for (int u = 0; u < 2; u++)                                          \
                 _Pragma("unroll")                                                \
                 for (int p = 0; p < 4; p++)                                      \
                     *(float2*)&zred[kg * 2176 + (rowA + 8 * u) * 34 + cq * 8 + p * 2] = \
                         *(float2*)&acc[u][p]; } while (0)
    #define ZRED_16()                                                             \
        do { _Pragma("unroll")                                                    \
             for (int u = 0; u < 2; u++)                                          \
                 _Pragma("unroll")                                                \
                 for (int p = 0; p < 4; p++)                                      \
                     *(float2*)&zred[kg2 * 1152 + (rowA + 8 * u) * 18 + (cq & 1) * 8 + p * 2] = \
                         *(float2*)&acc[u][p]; } while (0)

    // ---------------- P0: xw0 = x @ W0 (block-private, barrier-free) ----------
    for (int idx = tid; idx < Dsz * 4; idx += NTHR) {
        int gk = idx >> 2, p = idx & 3;
        *(float4*)&w_s[gk * 32 + p * 4] =
            *(const float4*)(W0 + (size_t)gk * Gsz + p * Hsz + j0);
    }
    __syncthreads();
    {
        LDG_X0(0, 0);
        for (int t = 0; t < Tsz; t++) {
            u64 acc[2][4] = {};
            STS_A(0); LDG_X0(t, 1);
            __syncthreads();
            COMPUTE_16(0, 0, 0); STS_A(1);
            if (t + 1 < Tsz) LDG_X0(t + 1, 0);
            __syncthreads();
            COMPUTE_16(1, 1, 0);
            ZRED_16();
            __syncthreads();
            if (tid < 256) {
                float4 o;
                #pragma unroll
                for (int v = 0; v < 4; v++) {
                    int c = xcp * 4 + v;
                    float s = 0.0f;
                    #pragma unroll
                    for (int m = 0; m < 16; m++) s += zred[m * 1152 + xb * 18 + c];
                    ((float*)&o)[v] = s;
                }
                *(float4*)(g_xwA + (((size_t)bc * Tsz + t) * Bsz + xb) * 16 + xcp * 4) = o;
            }
            __syncthreads();
        }
    }

    // ---------------- recurrent layers ----------------
    for (int layer = 0; layer < 3; layer++) {
        const int hasfil = (layer < 2);
        const float* Ul = (layer == 0) ? U0 : ((layer == 1) ? U1 : U2);
        const float* Wn = (layer == 0) ? W1 : W2;   // unused when !hasfil
        const float* bl = (layer == 0) ? b0 : ((layer == 1) ? b1 : b2);
        const float* xw_cur = (layer == 1) ? g_xwB : g_xwA;
        float*       xw_nxt = (layer == 0) ? g_xwB : g_xwA;

        if (layer > 0) bar_wait(&s_my);   // prior layer's tails done with g_hbuf

        for (int idx = tid; idx < Hsz * 4; idx += NTHR) {
            int gk = idx >> 2, p = idx & 3;
            *(float4*)&w_s[gk * 32 + p * 4] =
                *(const float4*)(Ul + (size_t)gk * Gsz + p * Hsz + j0);
            if (hasfil)
                *(float4*)&w_s[gk * 32 + 16 + p * 4] =
                    *(const float4*)(Wn + (size_t)gk * Gsz + p * Hsz + j0);
        }
        if (tid < 16) bias_s[tid] = bl[(tid >> 2) * Hsz + j0 + (tid & 3)];
        float c_reg = 0.0f, hval = 0.0f;
        if (tid < 256) g_hbuf[0][gb * Hsz + j0 + gj] = 0.0f;
        int cur = 0;
        bar_arrive(&s_my, grp);   // publish h_0

        for (int t = 0; t < Tsz; t++) {
            float xwv[4];
            if (tid < 256) {       // prefetch xw tile (block-private, pre-wait)
                const float* xp = xw_cur + (((size_t)bc * Tsz + t) * Bsz + gb) * 16 + gj;
                xwv[0] = xp[0]; xwv[1] = xp[4]; xwv[2] = xp[8]; xwv[3] = xp[12];
            }
            bar_wait(&s_my);
            const float* hsrc = g_hbuf[cur];
            u64 acc[2][4] = {};

            LDG_H(0); STS_A(0); LDG_H(1);
            __syncthreads();
            if (hasfil) COMPUTE_FIL(0, 0); else COMPUTE_16(0, 0, 0);
            STS_A(1); LDG_H(2);
            __syncthreads();
            if (hasfil) COMPUTE_FIL(1, 1); else COMPUTE_16(1, 1, 0);
            STS_A(0); LDG_H(3);
            __syncthreads();
            if (hasfil) COMPUTE_FIL(0, 2); else COMPUTE_16(0, 2, 0);
            STS_A(1);
            __syncthreads();
            if (hasfil) COMPUTE_FIL(1, 3); else COMPUTE_16(1, 3, 0);
            if (hasfil) ZRED_FIL(); else ZRED_16();
            __syncthreads();

            if (tid < 256) {
                float z[4];
                #pragma unroll
                for (int g = 0; g < 4; g++) {
                    int c = g * 4 + gj;
                    float s = xwv[g] + bias_s[c];
                    if (hasfil) {
                        #pragma unroll
                        for (int m = 0; m < 8; m++) s += zred[m * 2176 + gb * 34 + c];
                    } else {
                        #pragma unroll
                        for (int m = 0; m < 16; m++) s += zred[m * 1152 + gb * 18 + c];
                    }
                    z[g] = s;
                }
                float ig = fsig(z[0]);
                float fg = fsig(z[1]);
                float gg = ftanh(z[2]);
                float og = fsig(z[3]);
                c_reg = fg * c_reg + ig * gg;
                hval  = og * ftanh(c_reg);
                g_hbuf[cur ^ 1][gb * Hsz + j0 + gj] = hval;
            } else if (hasfil && tid < 512 && t > 0) {
                // filler gather: xw_{l+1}[t-1]
                int b = (tid - 256) >> 2, cp = tid & 3;
                float4 o;
                #pragma unroll
                for (int v = 0; v < 4; v++) {
                    int c = 16 + cp * 4 + v;
                    float s = 0.0f;
                    #pragma unroll
                    for (int m = 0; m < 8; m++) s += zred[m * 2176 + b * 34 + c];
                    ((float*)&o)[v] = s;
                }
                *(float4*)(xw_nxt + (((size_t)bc * Tsz + (t - 1)) * Bsz + b) * 16 + cp * 4) = o;
            }
            cur ^= 1;
            bar_arrive(&s_my, grp);
        }

        // ---- tail: xw_{l+1}[511] from final h; finals ----
        bar_wait(&s_my);
        if (hasfil) {
            const float* hsrc = g_hbuf[cur];
            u64 acc[2][4] = {};
            LDG_H(0); STS_A(0); LDG_H(1);
            __syncthreads();
            COMPUTE_16(0, 0, 16); STS_A(1); LDG_H(2);
            __syncthreads();
            COMPUTE_16(1, 1, 16); STS_A(0); LDG_H(3);
            __syncthreads();
            COMPUTE_16(0, 2, 16); STS_A(1);
            __syncthreads();
            COMPUTE_16(1, 3, 16);
            ZRED_16();
            __syncthreads();
            if (tid < 256) {
                float4 o;
                #pragma unroll
                for (int v = 0; v < 4; v++) {
                    int c = xcp * 4 + v;
                    float s = 0.0f;
                    #pragma unroll
                    for (int m = 0; m < 16; m++) s += zred[m * 1152 + xb * 18 + c];
                    ((float*)&o)[v] = s;
                }
                *(float4*)(xw_nxt + (((size_t)bc * Tsz + (Tsz - 1)) * Bsz + xb) * 16 + xcp * 4) = o;
            }
        }
        if (tid < 256) {
            size_t off = (size_t)gb * Hsz + j0 + gj;
            const size_t S = (size_t)Bsz * Hsz;
            if (layer == 0)      { out[1 * S + off] = hval; out[2 * S + off] = c_reg; }
            else if (layer == 1) { out[3 * S + off] = hval; out[4 * S + off] = c_reg; }
            else                 { out[off] = hval; out[5 * S + off] = hval; out[6 * S + off] = c_reg; }
        }
        bar_arrive(&s_my, grp);   // "my tail done" -> next layer's entry wait
    }
    #undef LDG_H
    #undef LDG_X0
    #undef STS_A
    #undef COMPUTE_FIL
    #undef COMPUTE_16
    #undef ZRED_FIL
    #undef ZRED_16
}

extern "C" void kernel_launch(void* const* d_in, const int* in_sizes, int n_in,
                              void* d_out, int out_size) {
    (void)in_sizes; (void)n_in; (void)out_size;
    static int attr_done = 0;
    if (!attr_done) {
        cudaFuncSetAttribute(lstm_kernel,
                             cudaFuncAttributeMaxDynamicSharedMemorySize, SMEM_BYTES);
        attr_done = 1;
    }
    lstm_kernel<<<NBLK, NTHR, SMEM_BYTES>>>(
        (const float*)d_in[0],
        (const float*)d_in[1], (const float*)d_in[2], (const float*)d_in[3],
        (const float*)d_in[4], (const float*)d_in[5], (const float*)d_in[6],
        (const float*)d_in[7], (const float*)d_in[8], (const float*)d_in[9],
        (float*)d_out);
}

// round 13
// speedup vs baseline: 1.6069x; 1.6069x over previous
#include <cuda_runtime.h>

// Stacked LSTM: B=64, T=512, D=256, H=512, 3 layers. fp32.
// R5 architecture (best: 15.67ms): persistent kernel, 128 blocks x 512
// threads, split-phase SINGLE-COUNTER grid barrier, block bc owns 4 hidden
// units (16 z-cols), 16-way warp k-split, packed f32x2 FFMA, weights
// resident in smem, x-region chunks computed between arrive and wait.
// R13 deltas: (1) 128-k double-buffered chunks, software-pipelined
// (STS/LDG ahead of compute, one sync per chunk); (2) seqout STG moved
// after bar_arrive (off the release-fence path).

#define Bsz 64
#define Tsz 512
#define Dsz 256
#define Hsz 512
#define Gsz 2048
#define NBLK 128
#define NTHR 512

typedef unsigned long long u64;

// smem floats: w_s [1024][16] 16384 | a_s [2][64][132] 16896 | zred [16][64][18] 18432 | bias 16
#define SM_WS   0
#define SM_AS   16384
#define SM_ZRED (16384 + 16896)
#define SM_BIAS (16384 + 16896 + 18432)
#define SMEM_FLOATS (SM_BIAS + 16)
#define SMEM_BYTES (SMEM_FLOATS * 4)
#define ASTRIDE 132
#define ABUF (64 * ASTRIDE)

__device__ float g_seqA[(size_t)Bsz * Tsz * Hsz];
__device__ float g_seqB[(size_t)Bsz * Tsz * Hsz];
__device__ float g_hbuf[2][Bsz * Hsz];
__device__ unsigned g_count = 0;
__device__ unsigned g_gen = 0;

// ---- split-phase grid barrier (single counter; snapshot-based) ----
__device__ __forceinline__ void bar_arrive(unsigned* s_my) {
    __syncthreads();
    if (threadIdx.x == 0) {
        unsigned my;
        asm volatile("ld.relaxed.gpu.u32 %0, [%1];" : "=r"(my) : "l"(&g_gen));
        *s_my = my;
        __threadfence();
        unsigned old = atomicAdd(&g_count, 1u);
        if (old == NBLK - 1) {
            g_count = 0;
            __threadfence();
            asm volatile("st.release.gpu.u32 [%0], %1;" :: "l"(&g_gen), "r"(my + 1u));
        }
    }
}
__device__ __forceinline__ void bar_wait(unsigned* s_my) {
    if (threadIdx.x == 0) {
        unsigned my = *s_my, g;
        do {
            asm volatile("ld.acquire.gpu.u32 %0, [%1];" : "=r"(g) : "l"(&g_gen));
        } while (g == my);
    }
    __syncthreads();
}

__device__ __forceinline__ float fsig(float x) {
    return __fdividef(1.0f, 1.0f + __expf(-x));
}
__device__ __forceinline__ float ftanh(float x) {
    float e = __expf(2.0f * x);
    return 1.0f - __fdividef(2.0f, e + 1.0f);
}
__device__ __forceinline__ void fma2(u64& d, u64 a, u64 b) {
    asm("fma.rn.f32x2 %0, %1, %2, %0;" : "+l"(d) : "l"(a), "l"(b));
}
__device__ __forceinline__ u64 rep2(float x) {
    u64 r;
    asm("mov.b64 %0, {%1, %1};" : "=l"(r) : "f"(x));
    return r;
}

extern "C" __global__ void __launch_bounds__(NTHR, 1)
lstm_kernel(const float* __restrict__ x0,
            const float* __restrict__ W0, const float* __restrict__ U0, const float* __restrict__ b0,
            const float* __restrict__ W1, const float* __restrict__ U1, const float* __restrict__ b1,
            const float* __restrict__ W2, const float* __restrict__ U2, const float* __restrict__ b2,
            float* __restrict__ out)
{
    extern __shared__ float smem[];
    float* w_s    = smem + SM_WS;     // [k][16]
    float* a_s    = smem + SM_AS;     // [2][64][ASTRIDE]
    float* zred   = smem + SM_ZRED;   // [16][64][18]
    float* bias_s = smem + SM_BIAS;   // [16]
    float* zpart  = a_s;              // gather scratch (a_s idle then): [4][256]
    __shared__ unsigned s_my;

    const int tid = threadIdx.x;
    const int bc  = blockIdx.x;
    const int j0  = bc * 4;
    // compute mapping: warp = k-split group (8 k per 128-k chunk)
    const int ks   = tid >> 5;        // 0..15
    const int lane = tid & 31;
    const int rg   = lane >> 1;       // 0..15 : rows rg + 16u, u<4
    const int cgp  = lane & 1;        // 0..1  : cols cgp*8 .. +7
    // staging mapping (128-k chunk: 64 rows x 128 k, 512 threads x 4 float4)
    const int sk4  = (tid & 31) * 4;  // 0..124
    const int srow = tid >> 5;        // rows srow + 16*r, r<4
    // gate mapping
    const int gb = (tid & 255) >> 2;
    const int gj = tid & 3;

    for (int layer = 0; layer < 3; layer++) {
        const float* Wl = (layer == 0) ? W0 : ((layer == 1) ? W1 : W2);
        const float* Ul = (layer == 0) ? U0 : ((layer == 1) ? U1 : U2);
        const float* bl = (layer == 0) ? b0 : ((layer == 1) ? b1 : b2);
        const float* xsrc = (layer == 0) ? x0 : ((layer == 1) ? g_seqA : g_seqB);
        float* seqout = (layer == 0) ? g_seqA : ((layer == 1) ? g_seqB : (float*)0);
        const int K_in = (layer == 0) ? Dsz : Hsz;
        const int Ktot = K_in + Hsz;        // 768 or 1024
        const int nch  = Ktot >> 7;         // 6 or 8 chunks
        const int nxc  = K_in >> 7;         // x-region chunks: 2 or 4

        // ---- weights resident in smem (once per layer) ----
        for (int idx = tid; idx < Ktot * 4; idx += NTHR) {
            int gk = idx >> 2, p = idx & 3;
            const float* wrow = (gk < K_in) ? (Wl + (size_t)gk * Gsz)
                                            : (Ul + (size_t)(gk - K_in) * Gsz);
            *(float4*)&w_s[gk * 16 + p * 4] = *(const float4*)(wrow + p * Hsz + j0);
        }
        if (tid < 16) bias_s[tid] = bl[(tid >> 2) * Hsz + j0 + (tid & 3)];
        float c_reg = 0.0f, hval = 0.0f;
        if (tid < 256) g_hbuf[0][gb * Hsz + j0 + gj] = 0.0f;
        int cur = 0;
        bar_arrive(&s_my);   // publish zeroed h_0

        float4 st[4];
        #define LDG_CHUNK(TT, CI)                                                     \
            do {                                                                      \
                int kb_ = (CI) << 7;                                                  \
                if (kb_ < K_in) {                                                     \
                    const float* s_ = xsrc + (size_t)(TT) * K_in + kb_ + sk4;         \
                    _Pragma("unroll")                                                 \
                    for (int r_ = 0; r_ < 4; r_++)                                    \
                        st[r_] = *(const float4*)(s_ + (size_t)(srow + 16 * r_) * Tsz * K_in); \
                } else {                                                              \
                    const float* s_ = hsrc + (kb_ - K_in) + sk4;                      \
                    _Pragma("unroll")                                                 \
                    for (int r_ = 0; r_ < 4; r_++)                                    \
                        st[r_] = *(const float4*)(s_ + (srow + 16 * r_) * Hsz);       \
                }                                                                     \
            } while (0)

        #define STS_CHUNK(BUF)                                                        \
            do {                                                                      \
                float* ad_ = a_s + (BUF) * ABUF;                                      \
                _Pragma("unroll")                                                     \
                for (int r_ = 0; r_ < 4; r_++)                                        \
                    *(float4*)&ad_[(srow + 16 * r_) * ASTRIDE + sk4] = st[r_];        \
            } while (0)

        // this warp's 8-k slice of 128-k chunk CI, from buffer BUF
        #define COMPUTE_CHUNK(BUF, CI)                                                \
            do {                                                                      \
                const float* wb = w_s + (((CI) << 7) + ks * 8) * 16;                  \
                const float* ab = a_s + (BUF) * ABUF + ks * 8;                        \
                _Pragma("unroll")                                                     \
                for (int kq = 0; kq < 2; kq++) {                                      \
                    float av[4][4];                                                   \
                    _Pragma("unroll")                                                 \
                    for (int u = 0; u < 4; u++)                                       \
                        *(float4*)av[u] = *(const float4*)&ab[(rg + 16 * u) * ASTRIDE + kq * 4]; \
                    _Pragma("unroll")                                                 \
                    for (int j = 0; j < 4; j++) {                                     \
                        const float* wr = wb + (kq * 4 + j) * 16 + cgp * 8;           \
                        ulonglong2 wlo = *(const ulonglong2*)wr;                      \
                        ulonglong2 whi = *(const ulonglong2*)(wr + 4);                \
                        _Pragma("unroll")                                             \
                        for (int u = 0; u < 4; u++) {                                 \
                            u64 ar = rep2(av[u][j]);                                  \
                            fma2(acc[u][0], ar, wlo.x);                               \
                            fma2(acc[u][1], ar, wlo.y);                               \
                            fma2(acc[u][2], ar, whi.x);                               \
                            fma2(acc[u][3], ar, whi.y);                               \
                        }                                                             \
                    }                                                                 \
                }                                                                     \
            } while (0)

        {
            const float* hsrc = g_hbuf[0];
            LDG_CHUNK(0, 0);   // step-0 chunk 0 (x region, barrier-independent)
            (void)hsrc;
        }

        for (int t = 0; t < Tsz; t++) {
            const float* hsrc = g_hbuf[cur];
            u64 acc[4][4] = {};

            // ---- x phase (overlaps other blocks' arrival) ----
            // pipeline: STS/LDG of upcoming chunks issued BEFORE compute
            STS_CHUNK(0);
            LDG_CHUNK(t, 1);
            __syncthreads();
            for (int ci = 0; ci < nxc; ci++) {
                if (ci + 1 < nxc) {
                    STS_CHUNK((ci + 1) & 1);
                    if (ci + 2 < nxc) LDG_CHUNK(t, ci + 2);
                }
                COMPUTE_CHUNK(ci & 1, ci);
                if (ci + 1 < nxc) __syncthreads();
            }

            // ---- wait for h_t, then h phase ----
            bar_wait(&s_my);   // ends with __syncthreads
            LDG_CHUNK(t, nxc);
            STS_CHUNK(nxc & 1);
            LDG_CHUNK(t, nxc + 1);
            __syncthreads();
            for (int ci = nxc; ci < nch; ci++) {
                if (ci + 1 < nch) {
                    STS_CHUNK((ci + 1) & 1);
                    if (ci + 2 < nch) LDG_CHUNK(t, ci + 2);
                }
                COMPUTE_CHUNK(ci & 1, ci);
                if (ci + 1 < nch) __syncthreads();
            }

            // ---- k-split partials ----
            #pragma unroll
            for (int u = 0; u < 4; u++)
                #pragma unroll
                for (int p = 0; p < 4; p++)
                    *(float2*)&zred[ks * 1152 + (rg + 16 * u) * 18 + cgp * 8 + p * 2] =
                        *(float2*)&acc[u][p];
            __syncthreads();

            // ---- split gather: upper half sums groups 8..15 into zpart ----
            if (tid >= 256) {
                #pragma unroll
                for (int g = 0; g < 4; g++) {
                    int o = gb * 18 + g * 4 + gj;
                    float s = 0.0f;
                    #pragma unroll
                    for (int k = 8; k < 16; k++) s += zred[k * 1152 + o];
                    zpart[g * 256 + (tid - 256)] = s;
                }
            }
            __syncthreads();

            // ---- gates (tid < 256: one thread per (b, j)) ----
            if (tid < 256) {
                float z[4];
                #pragma unroll
                for (int g = 0; g < 4; g++) {
                    int o = gb * 18 + g * 4 + gj;
                    float s = bias_s[g * 4 + gj] + zpart[g * 256 + tid];
                    #pragma unroll
                    for (int k = 0; k < 8; k++) s += zred[k * 1152 + o];
                    z[g] = s;
                }
                float ig = fsig(z[0]);
                float fg = fsig(z[1]);
                float gg = ftanh(z[2]);
                float og = fsig(z[3]);
                c_reg = fg * c_reg + ig * gg;
                hval  = og * ftanh(c_reg);
                g_hbuf[cur ^ 1][gb * Hsz + j0 + gj] = hval;
            }
            cur ^= 1;

            bar_arrive(&s_my);    // publish h_{t+1} (fence covers g_hbuf only)
            // seqout STG deferred past the arrive: visibility is guaranteed by
            // the NEXT arrive's fence, long before the next layer reads it.
            if (seqout && tid < 256)
                seqout[((size_t)(gb * Tsz + t)) * Hsz + j0 + gj] = hval;
            if (t + 1 < Tsz) LDG_CHUNK(t + 1, 0);  // prefetch next x chunk 0
        }
        bar_wait(&s_my);   // layer complete everywhere

        // ---- layer finals. Output: [out(=h2) | h0 | c0 | h1 | c1 | h2 | c2] ----
        if (tid < 256) {
            size_t off = (size_t)gb * Hsz + j0 + gj;
            const size_t S = (size_t)Bsz * Hsz;
            if (layer == 0)      { out[1 * S + off] = hval; out[2 * S + off] = c_reg; }
            else if (layer == 1) { out[3 * S + off] = hval; out[4 * S + off] = c_reg; }
            else                 { out[off] = hval; out[5 * S + off] = hval; out[6 * S + off] = c_reg; }
        }
        #undef LDG_CHUNK
        #undef STS_CHUNK
        #undef COMPUTE_CHUNK
    }
}

extern "C" void kernel_launch(void* const* d_in, const int* in_sizes, int n_in,
                              void* d_out, int out_size) {
    (void)in_sizes; (void)n_in; (void)out_size;
    static int attr_done = 0;
    if (!attr_done) {
        cudaFuncSetAttribute(lstm_kernel,
                             cudaFuncAttributeMaxDynamicSharedMemorySize, SMEM_BYTES);
        attr_done = 1;
    }
    lstm_kernel<<<NBLK, NTHR, SMEM_BYTES>>>(
        (const float*)d_in[0],
        (const float*)d_in[1], (const float*)d_in[2], (const float*)d_in[3],
        (const float*)d_in[4], (const float*)d_in[5], (const float*)d_in[6],
        (const float*)d_in[7], (const float*)d_in[8], (const float*)d_in[9],
        (float*)d_out);
}